// round 8
// baseline (speedup 1.0000x reference)
#include <cuda_runtime.h>
#include <stdint.h>

#define NBINS 29
#define DDIM  4096
#define CDIM  4
#define QDIM  32
#define NWARP 8
#define NSLOT 5          // ring slots per warp (prefetch distance 4)
#define NSLICE 20        // per row: 4 iters x (1 mask + 4 sim) slices
#define RPB   2          // rows (b,q) per block -> grid 1024 <= 1184 slots: 1 wave

__device__ __forceinline__ void cp_async16(uint32_t saddr, const void* gaddr) {
    asm volatile("cp.async.cg.shared.global [%0], [%1], 16;\n"
                 :: "r"(saddr), "l"(gaddr) : "memory");
}
#define CP_COMMIT() asm volatile("cp.async.commit_group;\n" ::: "memory")
#define CP_WAIT(N)  asm volatile("cp.async.wait_group %0;\n" :: "n"(N) : "memory")

// Two (b,q) rows per block so grid (1024) fits in one residency wave
// (148 SMs x 8 blocks = 1184 slots) -- R2/R4/R5 all parked at ~69% DRAM from
// the 1.73-wave tail. Mask is word-packed 0/1 (established R2-R5). cp.async
// stages mask+sim slices through per-warp smem rings (deep MLP, no reg cost);
// per-warp integer histograms, reduced to float per row.
__global__ __launch_bounds__(256, 8)
void count_hist_kernel(const float* __restrict__ sim,
                       const uint4* __restrict__ mask,
                       float* __restrict__ out)
{
    __shared__ int   hist[CDIM][NWARP][32];     // bin == bank (29 -> 32 pad)
    __shared__ uint4 ring[NWARP][NSLOT][32];    // 512B slices, per-warp private

    const int t    = threadIdx.x;
    const int warp = t >> 5;
    const int lane = t & 31;

    // smem address of this thread's slot-0 cell; slot stride = 512 bytes.
    const uint32_t rl =
        (uint32_t)__cvta_generic_to_shared(&ring[warp][0][lane]);
    const int cStride4 = QDIM * DDIM / 4;       // 32768

    #pragma unroll 1
    for (int r = 0; r < RPB; ++r) {
        const int bq = blockIdx.x * RPB + r;    // 0 .. B*Q-1
        const int b  = bq / QDIM;
        const int q  = bq - b * QDIM;

        // zero own warp's histograms (warp-private -> no sync needed before atomics)
        #pragma unroll
        for (int c = 0; c < CDIM; ++c)
            hist[c][warp][lane] = 0;

        const uint4* __restrict__ gm =
            mask + (size_t)bq * (DDIM / 4) + warp * 32 + lane;
        const float4* __restrict__ gs =
            reinterpret_cast<const float4*>(sim + ((size_t)b * CDIM * QDIM + q) * DDIM)
            + warp * 32 + lane;

        // slice j (0..19): it = j/5, k = j%5. k==0 -> mask; k>=1 -> sim c=k-1.
        // Prologue: slices 0..3 in flight.
        #pragma unroll
        for (int j = 0; j < 4; ++j) {
            const int it = j / 5, k = j % 5;
            const void* g = (k == 0) ? (const void*)(gm + it * 256)
                                     : (const void*)(gs + (k - 1) * cStride4 + it * 256);
            cp_async16(rl + (j % NSLOT) * 512, g);
            CP_COMMIT();
        }

        uint4 m;  // mask quad for the current iter

        #pragma unroll
        for (int j = 0; j < NSLICE; ++j) {
            const int slot = j % NSLOT;

            if      (NSLICE - 1 - j >= 3) CP_WAIT(3);
            else if (NSLICE - 1 - j == 2) CP_WAIT(2);
            else if (NSLICE - 1 - j == 1) CP_WAIT(1);
            else                          CP_WAIT(0);

            if ((j % 5) == 0) {
                m = ring[warp][slot][lane];     // park mask in regs for 4 slices
            } else {
                const int c = (j % 5) - 1;
                const float4 s =
                    *reinterpret_cast<const float4*>(&ring[warp][slot][lane]);
                // (int)((x+1.00001f)*14.0f) == trunc(((x+1.00001f)/2)*28) bit-exact
                const int b0 = (int)((s.x + 1.00001f) * 14.0f);
                const int b1 = (int)((s.y + 1.00001f) * 14.0f);
                const int b2 = (int)((s.z + 1.00001f) * 14.0f);
                const int b3 = (int)((s.w + 1.00001f) * 14.0f);
                if (m.x) atomicAdd(&hist[c][warp][b0], 1);
                if (m.y) atomicAdd(&hist[c][warp][b1], 1);
                if (m.z) atomicAdd(&hist[c][warp][b2], 1);
                if (m.w) atomicAdd(&hist[c][warp][b3], 1);
            }

            if (j + 4 < NSLICE) {
                const int jn = j + 4;
                const int it = jn / 5, k = jn % 5;
                const void* g = (k == 0) ? (const void*)(gm + it * 256)
                                         : (const void*)(gs + (k - 1) * cStride4 + it * 256);
                cp_async16(rl + (jn % NSLOT) * 512, g);
                CP_COMMIT();
            }
        }
        __syncthreads();   // all warps' histograms complete

        // reduce 8 warp-copies and write: C*NBINS = 116 outputs per row
        if (t < CDIM * NBINS) {
            const int c   = t / NBINS;
            const int bin = t - c * NBINS;
            int sum = 0;
            #pragma unroll
            for (int w = 0; w < NWARP; ++w) sum += hist[c][w][bin];
            out[(((size_t)b * CDIM + c) * QDIM + q) * NBINS + bin] = (float)sum;
        }
        __syncthreads();   // reduce reads done before next row re-zeroes hist
    }
}

extern "C" void kernel_launch(void* const* d_in, const int* in_sizes, int n_in,
                              void* d_out, int out_size)
{
    // sim is 4x larger (element count) than mask; pick by size for robustness.
    int i_sim  = 0, i_mask = 1;
    if (n_in >= 2 && in_sizes[1] > in_sizes[0]) { i_sim = 1; i_mask = 0; }

    const float* sim  = (const float*)d_in[i_sim];    // [B, C, Q, D] float32
    const uint4* mask = (const uint4*)d_in[i_mask];   // [B, Q, D] word-packed bool
    float*       out  = (float*)d_out;                // [B, C, Q, NBINS] float32

    const int rows   = in_sizes[i_mask] / DDIM;       // B*Q = 2048
    const int blocks = rows / RPB;                    // 1024 -> single wave

    count_hist_kernel<<<blocks, 256>>>(sim, mask, out);
}

// round 9
// speedup vs baseline: 1.0682x; 1.0682x over previous
#include <cuda_runtime.h>
#include <stdint.h>

#define NBINS 29
#define DDIM  4096
#define CDIM  4
#define QDIM  32
#define NWARP 8
#define QPB   8          // q rows per block (processed sequentially)
#define NSLICE 64        // 8 rows x (4 mask + 4 sim) slices of 4KB (512B/warp)
#define NSLOT 5          // ring slots per warp; prefetch distance 4 (no WAR)

__device__ __forceinline__ void cp_async16(uint32_t saddr, const void* gaddr) {
    asm volatile("cp.async.cg.shared.global [%0], [%1], 16;\n"
                 :: "r"(saddr), "l"(gaddr) : "memory");
}
#define CP_COMMIT() asm volatile("cp.async.commit_group;\n" ::: "memory")
#define CP_WAIT(N)  asm volatile("cp.async.wait_group %0;\n" :: "n"(N) : "memory")

// Block = (b, q-octet, c), c fastest in bid so the 4 c-blocks sharing a mask
// chunk are co-resident (mask re-reads hit L2; 33.5MB << 126MB L2). Each block
// reads TWO long sequential streams (128KB sim + 128KB mask) instead of five
// strided ones -- R2..R8 all parked at ~69% DRAM regardless of warp structure,
// pointing at HBM page locality as the limiter. Mask is word-packed 0/1
// (established R2+). Per-(q,warp) histograms => zero syncs until the epilogue.
__global__ __launch_bounds__(256, 7)
void count_hist_kernel(const float* __restrict__ sim,
                       const uint4* __restrict__ mask,
                       float* __restrict__ out)
{
    __shared__ int   hist[QPB][NWARP][32];      // bin == bank (29 -> 32 pad)
    __shared__ uint4 ring[NWARP][NSLOT][32];    // 512B slices, per-warp private

    const int t    = threadIdx.x;
    const int warp = t >> 5;
    const int lane = t & 31;

    const int bid = blockIdx.x;
    const int c   = bid & (CDIM - 1);           // fastest: L2 mask sharing
    const int qq  = (bid >> 2) & (QDIM / QPB - 1);
    const int b   = bid >> 4;
    const int q0  = qq * QPB;

    // zero own warp's histograms (warp-private -> no sync needed)
    #pragma unroll
    for (int q = 0; q < QPB; ++q)
        hist[q][warp][lane] = 0;

    // Per-thread bases in 16B vector units. Consecutive q rows are contiguous
    // in both tensors -> each stream is one 128KB sequential run.
    const uint4* __restrict__ gm =
        mask + ((size_t)(b * QDIM + q0)) * (DDIM / 4) + warp * 32 + lane;
    const float4* __restrict__ gs =
        reinterpret_cast<const float4*>(sim)
        + ((size_t)((b * CDIM + c) * QDIM + q0)) * (DDIM / 4) + warp * 32 + lane;

    const uint32_t rl =
        (uint32_t)__cvta_generic_to_shared(&ring[warp][0][lane]);

    // slice j (0..63): q = j>>3, chunk = (j>>1)&3, even j = mask, odd j = sim.
    // vec offset = q*1024 + chunk*256. Slot = j % 5 (distance-4 prefetch, the
    // overwritten slot was consumed one iteration earlier -> no WAR hazard).
    // Prologue: slices 0..3 in flight.
    #pragma unroll
    for (int j = 0; j < 4; ++j) {
        const int off = (j >> 3) * 1024 + ((j >> 1) & 3) * 256;
        const void* g = (j & 1) ? (const void*)(gs + off) : (const void*)(gm + off);
        cp_async16(rl + (j % NSLOT) * 512, g);
        CP_COMMIT();
    }

    uint4 m;  // mask quad: loaded on even slices, consumed on the next odd one

    #pragma unroll
    for (int j = 0; j < NSLICE; ++j) {
        // Always one trailing commit per iter (empty in tail) => exactly 4
        // groups pending at every wait; CP_WAIT(3) retires slice j.
        CP_WAIT(3);

        if ((j & 1) == 0) {
            m = ring[warp][j % NSLOT][lane];
        } else {
            const int q = j >> 3;
            const float4 s =
                *reinterpret_cast<const float4*>(&ring[warp][j % NSLOT][lane]);
            // (int)((x+1.00001f)*14.0f) == trunc(((x+1.00001f)/2)*28) bit-exact
            const int b0 = (int)((s.x + 1.00001f) * 14.0f);
            const int b1 = (int)((s.y + 1.00001f) * 14.0f);
            const int b2 = (int)((s.z + 1.00001f) * 14.0f);
            const int b3 = (int)((s.w + 1.00001f) * 14.0f);
            if (m.x) atomicAdd(&hist[q][warp][b0], 1);
            if (m.y) atomicAdd(&hist[q][warp][b1], 1);
            if (m.z) atomicAdd(&hist[q][warp][b2], 1);
            if (m.w) atomicAdd(&hist[q][warp][b3], 1);
        }

        if (j + 4 < NSLICE) {
            const int jn  = j + 4;
            const int off = (jn >> 3) * 1024 + ((jn >> 1) & 3) * 256;
            const void* g = (jn & 1) ? (const void*)(gs + off)
                                     : (const void*)(gm + off);
            cp_async16(rl + (jn % NSLOT) * 512, g);
        }
        CP_COMMIT();
    }
    __syncthreads();

    // reduce 8 warp-copies for all 8 q rows: QPB*NBINS = 232 outputs
    if (t < QPB * NBINS) {
        const int q   = t / NBINS;
        const int bin = t - q * NBINS;
        int sum = 0;
        #pragma unroll
        for (int w = 0; w < NWARP; ++w) sum += hist[q][w][bin];
        out[((size_t)((b * CDIM + c) * QDIM + q0 + q)) * NBINS + bin] = (float)sum;
    }
}

extern "C" void kernel_launch(void* const* d_in, const int* in_sizes, int n_in,
                              void* d_out, int out_size)
{
    // sim is 4x larger (element count) than mask; pick by size for robustness.
    int i_sim  = 0, i_mask = 1;
    if (n_in >= 2 && in_sizes[1] > in_sizes[0]) { i_sim = 1; i_mask = 0; }

    const float* sim  = (const float*)d_in[i_sim];    // [B, C, Q, D] float32
    const uint4* mask = (const uint4*)d_in[i_mask];   // [B, Q, D] word-packed bool
    float*       out  = (float*)d_out;                // [B, C, Q, NBINS] float32

    const int rows   = in_sizes[i_mask] / DDIM;       // B*Q = 2048
    const int blocks = (rows / QPB) * CDIM;           // 1024

    count_hist_kernel<<<blocks, 256>>>(sim, mask, out);
}

// round 13
// speedup vs baseline: 1.1113x; 1.0404x over previous
#include <cuda_runtime.h>
#include <stdint.h>

#define NBINS 29
#define DDIM  4096
#define CDIM  4
#define QDIM  32
#define NWARP 8
#define NSLOT 4          // ring slots per warp (prefetch distance 3)
#define NSLICE 20        // per block: 4 iters x (1 mask + 4 sim) slices
#define HSTRIDE 33       // sub-histogram stride: shifts banks by +1 (29 bins < 32)

__device__ __forceinline__ void cp_async16(uint32_t saddr, const void* gaddr) {
    asm volatile("cp.async.cg.shared.global [%0], [%1], 16;\n"
                 :: "r"(saddr), "l"(gaddr) : "memory");
}
#define CP_COMMIT() asm volatile("cp.async.commit_group;\n" ::: "memory")
#define CP_WAIT(N)  asm volatile("cp.async.wait_group %0;\n" :: "n"(N) : "memory")

// R5 structure (best: 31.2us) + lane-parity SPLIT HISTOGRAMS: each warp keeps
// 2 sub-histograms at a 33-word stride, selected by (lane&1). Halves the
// active lanes per atomic target set AND puts the two subsets on shifted bank
// sets -> shared-atomic conflict cycles ~halve. DRAM parked at 66-70% across
// six structural variants (R2..R9) while no pipe saturates: the smem atomic
// unit (~5 cyc x 7.1K ops/SM ~= 50-70% of kernel) is the hidden co-limiter.
// Mask is word-packed 0/1 (established R2+).
__global__ __launch_bounds__(256, 8)
void count_hist_kernel(const float* __restrict__ sim,
                       const uint4* __restrict__ mask,
                       float* __restrict__ out)
{
    // [c][warp][2*33]: sub0 bins at [0..28] (banks b), sub1 at [33..61] (banks b+1)
    __shared__ int   hist[CDIM][NWARP][2 * HSTRIDE];
    __shared__ uint4 ring[NWARP][NSLOT][32];    // 512B slices, per-warp private

    const int t    = threadIdx.x;
    const int warp = t >> 5;
    const int lane = t & 31;
    const int bq   = blockIdx.x;                // 0 .. B*Q-1
    const int b    = bq / QDIM;
    const int q    = bq - b * QDIM;

    #pragma unroll
    for (int i = t; i < CDIM * NWARP * 2 * HSTRIDE; i += 256)
        (&hist[0][0][0])[i] = 0;
    __syncthreads();

    // this thread's sub-histogram base: lane parity picks the sub-copy
    int* const h0 = &hist[0][warp][(lane & 1) * HSTRIDE];
    const int cOff = NWARP * 2 * HSTRIDE;       // int stride between c planes

    const uint4* __restrict__ gm =
        mask + (size_t)bq * (DDIM / 4) + warp * 32 + lane;
    const float4* __restrict__ gs =
        reinterpret_cast<const float4*>(sim + ((size_t)b * CDIM * QDIM + q) * DDIM)
        + warp * 32 + lane;
    const int cStride4 = QDIM * DDIM / 4;       // 32768

    const uint32_t rl =
        (uint32_t)__cvta_generic_to_shared(&ring[warp][0][lane]);

    // slice j (0..19): it = j/5, k = j%5. k==0 -> mask; k>=1 -> sim c=k-1.
    // Prologue: slices 0..2 in flight (distance-3; slot j%4 overwritten one
    // iteration after consumption -> no WAR hazard).
    #pragma unroll
    for (int j = 0; j < 3; ++j) {
        const int it = j / 5, k = j % 5;
        const void* g = (k == 0) ? (const void*)(gm + it * 256)
                                 : (const void*)(gs + (k - 1) * cStride4 + it * 256);
        cp_async16(rl + (j % NSLOT) * 512, g);
        CP_COMMIT();
    }

    uint4 m;  // mask quad for the current iter

    #pragma unroll
    for (int j = 0; j < NSLICE; ++j) {
        // One trailing commit per iter (empty in tail) => exactly 3 groups
        // pending at every wait; CP_WAIT(2) retires slice j.
        CP_WAIT(2);

        if ((j % 5) == 0) {
            m = ring[warp][j % NSLOT][lane];    // park mask in regs for 4 slices
        } else {
            const int c = (j % 5) - 1;
            int* const hc = h0 + c * cOff;
            const float4 s =
                *reinterpret_cast<const float4*>(&ring[warp][j % NSLOT][lane]);
            // (int)((x+1.00001f)*14.0f) == trunc(((x+1.00001f)/2)*28) bit-exact
            const int b0 = (int)((s.x + 1.00001f) * 14.0f);
            const int b1 = (int)((s.y + 1.00001f) * 14.0f);
            const int b2 = (int)((s.z + 1.00001f) * 14.0f);
            const int b3 = (int)((s.w + 1.00001f) * 14.0f);
            if (m.x) atomicAdd(hc + b0, 1);
            if (m.y) atomicAdd(hc + b1, 1);
            if (m.z) atomicAdd(hc + b2, 1);
            if (m.w) atomicAdd(hc + b3, 1);
        }

        if (j + 3 < NSLICE) {
            const int jn = j + 3;
            const int it = jn / 5, k = jn % 5;
            const void* g = (k == 0) ? (const void*)(gm + it * 256)
                                     : (const void*)(gs + (k - 1) * cStride4 + it * 256);
            cp_async16(rl + (jn % NSLOT) * 512, g);
        }
        CP_COMMIT();
    }
    __syncthreads();

    // reduce 8 warps x 2 sub-copies and write: C*NBINS = 116 outputs
    if (t < CDIM * NBINS) {
        const int c   = t / NBINS;
        const int bin = t - c * NBINS;
        int sum = 0;
        #pragma unroll
        for (int w = 0; w < NWARP; ++w)
            sum += hist[c][w][bin] + hist[c][w][HSTRIDE + bin];
        out[(((size_t)b * CDIM + c) * QDIM + q) * NBINS + bin] = (float)sum;
    }
}

extern "C" void kernel_launch(void* const* d_in, const int* in_sizes, int n_in,
                              void* d_out, int out_size)
{
    // sim is 4x larger (element count) than mask; pick by size for robustness.
    int i_sim  = 0, i_mask = 1;
    if (n_in >= 2 && in_sizes[1] > in_sizes[0]) { i_sim = 1; i_mask = 0; }

    const float* sim  = (const float*)d_in[i_sim];    // [B, C, Q, D] float32
    const uint4* mask = (const uint4*)d_in[i_mask];   // [B, Q, D] word-packed bool
    float*       out  = (float*)d_out;                // [B, C, Q, NBINS] float32

    const int blocks = in_sizes[i_mask] / DDIM;       // B*Q = 2048

    count_hist_kernel<<<blocks, 256>>>(sim, mask, out);
}

// round 15
// speedup vs baseline: 1.1569x; 1.0410x over previous
#include <cuda_runtime.h>
#include <stdint.h>

#define NBINS 29
#define DDIM  4096
#define CDIM  4
#define QDIM  32
#define NWARP 8
#define NSLOT 5          // ring slots per warp (prefetch distance 4)
#define NSLICE 20        // per block: 4 iters x (1 mask + 4 sim) slices

// cp.async with an L2 evict-first cache hint: all input is read-once, so mark
// the stream transient to cut LTS allocation/eviction overhead.
__device__ __forceinline__ void cp_async16_ef(uint32_t saddr, const void* gaddr,
                                              uint64_t pol) {
    asm volatile("cp.async.cg.shared.global.L2::cache_hint [%0], [%1], 16, %2;\n"
                 :: "r"(saddr), "l"(gaddr), "l"(pol) : "memory");
}
#define CP_COMMIT() asm volatile("cp.async.commit_group;\n" ::: "memory")
#define CP_WAIT(N)  asm volatile("cp.async.wait_group %0;\n" :: "n"(N) : "memory")

// R5 structure (proven best: 31.232us) + L2::evict_first policy on all staged
// loads. Six structural variants (R2..R13) all park at 5.45-5.5 TB/s; warp
// structure, address pattern, waves, and atomic conflicts are each ruled out
// as limiters. Cache-allocation policy is the last untested axis on the
// memory path. Mask is word-packed 0/1 (established R2+). Per-warp integer
// histograms in shared memory, reduced to float at the end.
__global__ __launch_bounds__(256, 8)
void count_hist_kernel(const float* __restrict__ sim,
                       const uint4* __restrict__ mask,
                       float* __restrict__ out)
{
    __shared__ int   hist[CDIM][NWARP][32];     // bin == bank (29 -> 32 pad)
    __shared__ uint4 ring[NWARP][NSLOT][32];    // 512B slices, per-warp private

    const int t    = threadIdx.x;
    const int warp = t >> 5;
    const int lane = t & 31;
    const int bq   = blockIdx.x;                // 0 .. B*Q-1
    const int b    = bq / QDIM;
    const int q    = bq - b * QDIM;

    uint64_t pol;
    asm("createpolicy.fractional.L2::evict_first.b64 %0, 1.0;" : "=l"(pol));

    #pragma unroll
    for (int i = t; i < CDIM * NWARP * 32; i += 256)
        (&hist[0][0][0])[i] = 0;
    __syncthreads();

    // Per-thread global bases (16B vector units), offset warp*32+lane.
    const uint4* __restrict__ gm =
        mask + (size_t)bq * (DDIM / 4) + warp * 32 + lane;
    const float4* __restrict__ gs =
        reinterpret_cast<const float4*>(sim + ((size_t)b * CDIM * QDIM + q) * DDIM)
        + warp * 32 + lane;
    const int cStride4 = QDIM * DDIM / 4;       // 32768

    const uint32_t rl =
        (uint32_t)__cvta_generic_to_shared(&ring[warp][0][lane]);

    // slice j (0..19): it = j/5, k = j%5. k==0 -> mask; k>=1 -> sim c=k-1.
    // Prologue: slices 0..3 in flight.
    #pragma unroll
    for (int j = 0; j < 4; ++j) {
        const int it = j / 5, k = j % 5;
        const void* g = (k == 0) ? (const void*)(gm + it * 256)
                                 : (const void*)(gs + (k - 1) * cStride4 + it * 256);
        cp_async16_ef(rl + (j % NSLOT) * 512, g, pol);
        CP_COMMIT();
    }

    uint4 m;  // mask quad for the current iter

    #pragma unroll
    for (int j = 0; j < NSLICE; ++j) {
        const int slot = j % NSLOT;

        // Wait for slice j: allow min(3, 19-j) newer groups to stay pending.
        if      (NSLICE - 1 - j >= 3) CP_WAIT(3);
        else if (NSLICE - 1 - j == 2) CP_WAIT(2);
        else if (NSLICE - 1 - j == 1) CP_WAIT(1);
        else                          CP_WAIT(0);

        if ((j % 5) == 0) {
            m = ring[warp][slot][lane];         // park mask in regs for 4 slices
        } else {
            const int c = (j % 5) - 1;
            const float4 s =
                *reinterpret_cast<const float4*>(&ring[warp][slot][lane]);
            // (int)((x+1.00001f)*14.0f) == trunc(((x+1.00001f)/2)*28) bit-exact
            const int b0 = (int)((s.x + 1.00001f) * 14.0f);
            const int b1 = (int)((s.y + 1.00001f) * 14.0f);
            const int b2 = (int)((s.z + 1.00001f) * 14.0f);
            const int b3 = (int)((s.w + 1.00001f) * 14.0f);
            if (m.x) atomicAdd(&hist[c][warp][b0], 1);
            if (m.y) atomicAdd(&hist[c][warp][b1], 1);
            if (m.z) atomicAdd(&hist[c][warp][b2], 1);
            if (m.w) atomicAdd(&hist[c][warp][b3], 1);
        }

        // Issue slice j+4 into the slot freed at j-1.
        if (j + 4 < NSLICE) {
            const int jn = j + 4;
            const int it = jn / 5, k = jn % 5;
            const void* g = (k == 0) ? (const void*)(gm + it * 256)
                                     : (const void*)(gs + (k - 1) * cStride4 + it * 256);
            cp_async16_ef(rl + (jn % NSLOT) * 512, g, pol);
            CP_COMMIT();
        }
    }
    __syncthreads();

    // reduce 8 warp-copies and write: C*NBINS = 116 outputs per block
    if (t < CDIM * NBINS) {
        const int c   = t / NBINS;
        const int bin = t - c * NBINS;
        int sum = 0;
        #pragma unroll
        for (int w = 0; w < NWARP; ++w) sum += hist[c][w][bin];
        out[(((size_t)b * CDIM + c) * QDIM + q) * NBINS + bin] = (float)sum;
    }
}

extern "C" void kernel_launch(void* const* d_in, const int* in_sizes, int n_in,
                              void* d_out, int out_size)
{
    // sim is 4x larger (element count) than mask; pick by size for robustness.
    int i_sim  = 0, i_mask = 1;
    if (n_in >= 2 && in_sizes[1] > in_sizes[0]) { i_sim = 1; i_mask = 0; }

    const float* sim  = (const float*)d_in[i_sim];    // [B, C, Q, D] float32
    const uint4* mask = (const uint4*)d_in[i_mask];   // [B, Q, D] word-packed bool
    float*       out  = (float*)d_out;                // [B, C, Q, NBINS] float32

    const int blocks = in_sizes[i_mask] / DDIM;       // B*Q = 2048

    count_hist_kernel<<<blocks, 256>>>(sim, mask, out);
}